// round 4
// baseline (speedup 1.0000x reference)
#include <cuda_runtime.h>
#include <cstdint>

// Problem constants
#define BB   2
#define SS   2048
#define DIMM 1024
#define HH   16
#define DD   64
#define FF   32      // S / 64
#define EPSF 1e-6f

// Scratch (static device globals; no dynamic allocation)
__device__ float g_raw[3][BB * SS * DIMM];        // raw projections [b,s,dim]
__device__ float g_T[3][BB * HH * SS * DD];       // q,k,v in [b,h,s,d]

// ---------------------------------------------------------------------------
// SGEMM: C[m,n] = sum_k X[m,k] * W[n,k]   (X: 4096x1024, W: 1024x1024)
// blockIdx.z selects wq/wk/wv. Tile 128x128xBK8, 256 threads, 8x8/thread.
// ---------------------------------------------------------------------------
__global__ __launch_bounds__(256) void sgemm_nt(const float* __restrict__ X,
                                                const float* __restrict__ Wq,
                                                const float* __restrict__ Wk,
                                                const float* __restrict__ Wv)
{
    const float* W = (blockIdx.z == 0) ? Wq : (blockIdx.z == 1 ? Wk : Wv);
    float* C = g_raw[blockIdx.z];

    __shared__ float As[8][132];
    __shared__ float Bs[8][132];

    int tid = threadIdx.x;
    int m0 = blockIdx.y * 128, n0 = blockIdx.x * 128;
    int tx = tid & 15, ty = tid >> 4;

    float acc[8][8];
#pragma unroll
    for (int i = 0; i < 8; i++)
#pragma unroll
        for (int jj = 0; jj < 8; jj++) acc[i][jj] = 0.f;

    int lr = tid >> 1;         // 0..127 row of tile
    int lc = (tid & 1) * 4;    // 0 or 4 (k offset)
    const float* Aptr = X + (size_t)(m0 + lr) * 1024 + lc;
    const float* Bptr = W + (size_t)(n0 + lr) * 1024 + lc;

    for (int k0 = 0; k0 < 1024; k0 += 8) {
        float4 av = *(const float4*)(Aptr + k0);
        float4 bv = *(const float4*)(Bptr + k0);
        __syncthreads();
        As[lc + 0][lr] = av.x; As[lc + 1][lr] = av.y;
        As[lc + 2][lr] = av.z; As[lc + 3][lr] = av.w;
        Bs[lc + 0][lr] = bv.x; Bs[lc + 1][lr] = bv.y;
        Bs[lc + 2][lr] = bv.z; Bs[lc + 3][lr] = bv.w;
        __syncthreads();
#pragma unroll
        for (int kk = 0; kk < 8; kk++) {
            float a[8], b[8];
#pragma unroll
            for (int u = 0; u < 8; u++) a[u] = As[kk][ty * 8 + u];
#pragma unroll
            for (int u = 0; u < 8; u++) b[u] = Bs[kk][tx * 8 + u];
#pragma unroll
            for (int i = 0; i < 8; i++)
#pragma unroll
                for (int jj = 0; jj < 8; jj++)
                    acc[i][jj] = fmaf(a[i], b[jj], acc[i][jj]);
        }
    }
#pragma unroll
    for (int i = 0; i < 8; i++) {
        float4 v0 = make_float4(acc[i][0], acc[i][1], acc[i][2], acc[i][3]);
        float4 v1 = make_float4(acc[i][4], acc[i][5], acc[i][6], acc[i][7]);
        float* cp = C + (size_t)(m0 + ty * 8 + i) * 1024 + n0 + tx * 8;
        *(float4*)cp = v0;
        *(float4*)(cp + 4) = v1;
    }
}

// ---------------------------------------------------------------------------
// Epilogue: rmsnorm(q,k) + rope + scale, transpose all to [b,h,s,d]
// One warp per (b,s,h) row of 64; lane handles d0=2*lane, d1=2*lane+1.
// ---------------------------------------------------------------------------
__global__ __launch_bounds__(128) void qkv_epilogue(const float* __restrict__ cosT,
                                                    const float* __restrict__ sinT,
                                                    const float* __restrict__ gq,
                                                    const float* __restrict__ gk)
{
    int warp = blockIdx.x * 4 + (threadIdx.x >> 5);
    int lane = threadIdx.x & 31;
    int h  = warp & 15;
    int bs = warp >> 4;           // b*S + s
    int s  = bs & (SS - 1);
    int b  = bs >> 11;
    int d0 = lane * 2, d1 = d0 + 1;
    size_t src = (size_t)bs * 1024 + h * 64;
    size_t dst = ((size_t)(b * HH + h) * SS + s) * 64;

    float c  = cosT[s * 64 + d0];
    float sn = sinT[s * 64 + d0];
    const float SCALE = 0.35355339059327373f;   // 64^-0.25

    // Q
    {
        float x0 = g_raw[0][src + d0], x1 = g_raw[0][src + d1];
        float ssum = x0 * x0 + x1 * x1;
#pragma unroll
        for (int m = 16; m > 0; m >>= 1) ssum += __shfl_xor_sync(0xffffffffu, ssum, m);
        float r = rsqrtf(ssum * (1.0f / 64.0f) + EPSF);
        x0 *= r * gq[d0]; x1 *= r * gq[d1];
        g_T[0][dst + d0] = (x0 * c - x1 * sn) * SCALE;
        g_T[0][dst + d1] = (x1 * c + x0 * sn) * SCALE;
    }
    // K
    {
        float x0 = g_raw[1][src + d0], x1 = g_raw[1][src + d1];
        float ssum = x0 * x0 + x1 * x1;
#pragma unroll
        for (int m = 16; m > 0; m >>= 1) ssum += __shfl_xor_sync(0xffffffffu, ssum, m);
        float r = rsqrtf(ssum * (1.0f / 64.0f) + EPSF);
        x0 *= r * gk[d0]; x1 *= r * gk[d1];
        g_T[1][dst + d0] = (x0 * c - x1 * sn) * SCALE;
        g_T[1][dst + d1] = (x1 * c + x0 * sn) * SCALE;
    }
    // V (plain transpose)
    g_T[2][dst + d0] = g_raw[2][src + d0];
    g_T[2][dst + d1] = g_raw[2][src + d1];
}

// ---------------------------------------------------------------------------
// Monarch iterations. One CTA per (b,h,g). 256 threads.
// group = tid/4 -> (a = group/8 [=warp id], j = group%8), t4 = tid%4 (d-chunk of 16).
// Shared: Ls[32][8][68] (L/M, padded), Rs[32][8][8][8], Ks[2][4096] (K/V tiles),
//         Os[8][8+pad] o-tile.
// ---------------------------------------------------------------------------
#define LS_FLOATS  (32 * 8 * 68)          // 17408
#define RS_FLOATS  (32 * 8 * 8 * 8)       // 16384
#define KS_FLOATS  (2 * 4096)             // 8192
#define OS_FLOATS  (8 * 8 * 68 / 8 * 8)   // 4352 = 64*68
#define SMEM_FLOATS (LS_FLOATS + RS_FLOATS + KS_FLOATS + 4352)
#define SMEM_BYTES  (SMEM_FLOATS * 4)

__device__ __forceinline__ void issue_tile(int step, int g,
                                           const float* __restrict__ Kp,
                                           const float* __restrict__ Vp,
                                           uint32_t Ks_base, int tid)
{
    int per   = g + 1;
    int phase = step / per;                  // 0,1 -> K ; 2 -> V
    int f     = step - phase * per;
    const float* src = ((phase < 2) ? Kp : Vp) + (size_t)f * 4096;
    uint32_t dstb = Ks_base + (uint32_t)(step & 1) * (4096u * 4u);
#pragma unroll
    for (int u = 0; u < 4; u++) {
        int idx4 = tid + u * 256;
        asm volatile("cp.async.cg.shared.global [%0], [%1], 16;"
                     :: "r"(dstb + idx4 * 16), "l"(src + idx4 * 4) : "memory");
    }
    asm volatile("cp.async.commit_group;" ::: "memory");
}

__global__ void __launch_bounds__(256, 1) monarch_kernel(float* __restrict__ out)
{
    const int g = blockIdx.x, h = blockIdx.y, b = blockIdx.z;
    const int tid = threadIdx.x;
    const int t4  = tid & 3;
    const int grp = tid >> 2;
    const int j   = grp & 7;
    const int a   = grp >> 3;    // warp id

    extern __shared__ float sm[];
    float* Ls = sm;
    float* Rs = sm + LS_FLOATS;
    float* Ks = Rs + RS_FLOATS;
    float* Os = Ks + KS_FLOATS;
    uint32_t Ks_base = (uint32_t)__cvta_generic_to_shared(Ks);

    const int bh = b * HH + h;
    const float* Q  = g_T[0] + ((size_t)bh * SS + g * 64) * 64;
    const float* Kp = g_T[1] + (size_t)bh * SS * 64;
    const float* Vp = g_T[2] + (size_t)bh * SS * 64;

    // init L[f][j][k][i] = (f<=g) * delta(k,i)
    for (int idx = tid; idx < 32 * 8 * 64; idx += 256) {
        int f   = idx >> 9;
        int rem = idx & 511;
        int jj  = rem >> 6;
        int e   = rem & 63;
        int k   = e >> 3, i = e & 7;
        Ls[(f * 8 + jj) * 68 + e] = (f <= g && k == i) ? 1.0f : 0.0f;
    }

    // q block -> registers: qreg[i][dd], thread owns (j, d-chunk t4)
    float qreg[8][16];
#pragma unroll
    for (int i = 0; i < 8; i++) {
        const float4* qp = (const float4*)(Q + (i * 8 + j) * 64 + t4 * 16);
#pragma unroll
        for (int u = 0; u < 4; u++) {
            float4 v = qp[u];
            qreg[i][u * 4 + 0] = v.x; qreg[i][u * 4 + 1] = v.y;
            qreg[i][u * 4 + 2] = v.z; qreg[i][u * 4 + 3] = v.w;
        }
    }
    __syncthreads();

    const int nsteps = 3 * (g + 1);
    issue_tile(0, g, Kp, Vp, Ks_base, tid);
    int step = 0;

    const float NEGINF = __int_as_float(0xff800000);

    for (int it = 0; it < 2; it++) {
        for (int f = 0; f <= g; f++, step++) {
            if (step + 1 < nsteps) {
                issue_tile(step + 1, g, Kp, Vp, Ks_base, tid);
                asm volatile("cp.async.wait_group 1;" ::: "memory");
            } else {
                asm volatile("cp.async.wait_group 0;" ::: "memory");
            }
            __syncthreads();

            const float* kt = Ks + (step & 1) * 4096 + a * 512;   // k-row a: [l][64]
            float* Lrow = Ls + (f * 8 + j) * 68 + a * 8;

            float Lw[8];
#pragma unroll
            for (int i = 0; i < 8; i++) Lw[i] = Lrow[i];
            float cR = 0.f;
#pragma unroll
            for (int i = 0; i < 8; i++) cR += Lw[i];

            // aR[dd] = sum_i Lw[i] * q[i][dd]
            float aR[16];
#pragma unroll
            for (int dd = 0; dd < 16; dd++) {
                float s = 0.f;
#pragma unroll
                for (int i = 0; i < 8; i++) s = fmaf(Lw[i], qreg[i][dd], s);
                aR[dd] = s;
            }

            // bR partials over this thread's d-chunk
            float p[8];
#pragma unroll
            for (int l = 0; l < 8; l++) {
                const float* kv = kt + l * 64 + t4 * 16;
                float s = 0.f;
#pragma unroll
                for (int dd = 0; dd < 16; dd++) s = fmaf(aR[dd], kv[dd], s);
                p[l] = s;
            }
#pragma unroll
            for (int l = 0; l < 8; l++) {
                p[l] += __shfl_xor_sync(0xffffffffu, p[l], 1);
                p[l] += __shfl_xor_sync(0xffffffffu, p[l], 2);
            }

            // softmax over l of bR/(cR+eps)
            float inv = 1.0f / (cR + EPSF);
            float mx = NEGINF;
#pragma unroll
            for (int l = 0; l < 8; l++) { p[l] *= inv; mx = fmaxf(mx, p[l]); }
            float ssum = 0.f;
#pragma unroll
            for (int l = 0; l < 8; l++) { p[l] = __expf(p[l] - mx); ssum += p[l]; }
            float rinv = 1.0f / ssum;
            float cL = 0.f;
#pragma unroll
            for (int l = 0; l < 8; l++) {
                p[l] *= rinv;
                cL = fmaf(p[l], __logf(fmaxf(p[l], 1e-38f)), cL);
            }

            if (t4 == 0) {
                float* rp = Rs + ((f * 8 + a) * 8 + j) * 8;
#pragma unroll
                for (int l = 0; l < 8; l++) rp[l] = p[l];
            }

            // aL[dd] = sum_l R[l] * k[l][dd]
            float aL[16];
#pragma unroll
            for (int dd = 0; dd < 16; dd++) aL[dd] = 0.f;
#pragma unroll
            for (int l = 0; l < 8; l++) {
                const float* kv = kt + l * 64 + t4 * 16;
#pragma unroll
                for (int dd = 0; dd < 16; dd++) aL[dd] = fmaf(p[l], kv[dd], aL[dd]);
            }

            // bL[i] = sum_d aL[dd] * q[i][dd]  (partial, then 4-lane reduce)
            float bL[8];
#pragma unroll
            for (int i = 0; i < 8; i++) {
                float s = 0.f;
#pragma unroll
                for (int dd = 0; dd < 16; dd++) s = fmaf(aL[dd], qreg[i][dd], s);
                bL[i] = s;
            }
#pragma unroll
            for (int i = 0; i < 8; i++) {
                bL[i] += __shfl_xor_sync(0xffffffffu, bL[i], 1);
                bL[i] += __shfl_xor_sync(0xffffffffu, bL[i], 2);
            }

            // M overwrite L (same group owns this row segment)
            if (t4 == 0) {
#pragma unroll
                for (int i = 0; i < 8; i++) Lrow[i] = bL[i] - cL;
            }
            __syncthreads();
        }

        // L softmax over (f<=g, k) for each (j, i=a); t4 strides f
        {
            float mx = NEGINF;
            for (int f = t4; f <= g; f += 4) {
                const float* Mr = Ls + (f * 8 + j) * 68;
#pragma unroll
                for (int k = 0; k < 8; k++) mx = fmaxf(mx, Mr[k * 8 + a]);
            }
            mx = fmaxf(mx, __shfl_xor_sync(0xffffffffu, mx, 1));
            mx = fmaxf(mx, __shfl_xor_sync(0xffffffffu, mx, 2));
            float ssum = 0.f;
            for (int f = t4; f <= g; f += 4) {
                const float* Mr = Ls + (f * 8 + j) * 68;
#pragma unroll
                for (int k = 0; k < 8; k++) ssum += __expf(Mr[k * 8 + a] - mx);
            }
            ssum += __shfl_xor_sync(0xffffffffu, ssum, 1);
            ssum += __shfl_xor_sync(0xffffffffu, ssum, 2);
            float rs = 1.0f / ssum;
            for (int f = t4; f <= g; f += 4) {
                float* Mr = Ls + (f * 8 + j) * 68;
#pragma unroll
                for (int k = 0; k < 8; k++)
                    Mr[k * 8 + a] = __expf(Mr[k * 8 + a] - mx) * rs;
            }
        }
        __syncthreads();
    }

    // o / out: out[i,j,d] = sum_{f,k} L[f,j,k,i] * (sum_l R[f,k,j,l] v[f,k,l,d])
    float oacc[16];
#pragma unroll
    for (int dd = 0; dd < 16; dd++) oacc[dd] = 0.f;

    for (int f = 0; f <= g; f++, step++) {
        if (step + 1 < nsteps) {
            issue_tile(step + 1, g, Kp, Vp, Ks_base, tid);
            asm volatile("cp.async.wait_group 1;" ::: "memory");
        } else {
            asm volatile("cp.async.wait_group 0;" ::: "memory");
        }
        __syncthreads();

        const float* vt = Ks + (step & 1) * 4096 + a * 512;   // v-row k=a
        // phase A: o_f[k=a][j][dchunk]
        const float* rp = Rs + ((f * 8 + a) * 8 + j) * 8;
        float Rv[8];
#pragma unroll
        for (int l = 0; l < 8; l++) Rv[l] = rp[l];
        float ov[16];
#pragma unroll
        for (int dd = 0; dd < 16; dd++) ov[dd] = 0.f;
#pragma unroll
        for (int l = 0; l < 8; l++) {
            const float* vv = vt + l * 64 + t4 * 16;
#pragma unroll
            for (int dd = 0; dd < 16; dd++) ov[dd] = fmaf(Rv[l], vv[dd], ov[dd]);
        }
        float* op = Os + (a * 8 + j) * 68 + t4 * 16;
#pragma unroll
        for (int dd = 0; dd < 16; dd++) op[dd] = ov[dd];
        __syncthreads();

        // phase B: out[i=a][j][dchunk] += sum_k L[f][j][k][i] * o_f[k][j][dchunk]
        const float* Lrow = Ls + (f * 8 + j) * 68;
#pragma unroll
        for (int k = 0; k < 8; k++) {
            float lw = Lrow[k * 8 + a];
            const float* op2 = Os + (k * 8 + j) * 68 + t4 * 16;
#pragma unroll
            for (int dd = 0; dd < 16; dd++) oacc[dd] = fmaf(lw, op2[dd], oacc[dd]);
        }
        __syncthreads();
    }

    // write out[b][g*64 + i*8 + j][h*64 + d]
    float* po = out + ((size_t)b * SS + g * 64 + a * 8 + j) * DIMM + h * 64 + t4 * 16;
#pragma unroll
    for (int dd = 0; dd < 16; dd += 4) {
        float4 v = make_float4(oacc[dd], oacc[dd + 1], oacc[dd + 2], oacc[dd + 3]);
        *(float4*)(po + dd) = v;
    }
}

// ---------------------------------------------------------------------------
extern "C" void kernel_launch(void* const* d_in, const int* in_sizes, int n_in,
                              void* d_out, int out_size)
{
    const float* x    = (const float*)d_in[0];
    const float* cosT = (const float*)d_in[1];
    const float* sinT = (const float*)d_in[2];
    const float* wq   = (const float*)d_in[3];
    const float* wk   = (const float*)d_in[4];
    const float* wv   = (const float*)d_in[5];
    const float* gq   = (const float*)d_in[6];
    const float* gk   = (const float*)d_in[7];
    float* out = (float*)d_out;

    cudaFuncSetAttribute(monarch_kernel,
                         cudaFuncAttributeMaxDynamicSharedMemorySize, SMEM_BYTES);

    sgemm_nt<<<dim3(8, 32, 3), 256>>>(x, wq, wk, wv);
    qkv_epilogue<<<(BB * SS * HH) / 4, 128>>>(cosT, sinT, gq, gk);
    monarch_kernel<<<dim3(FF, HH, BB), 256, SMEM_BYTES>>>(out);
}